// round 8
// baseline (speedup 1.0000x reference)
#include <cuda_runtime.h>
#include <cuda_fp16.h>
#include <math.h>
#include <stdint.h>

#define NEGV -65504.0f

// ---------------- scratch (device globals; no allocations allowed) ----------
__device__ float  g_scores[64 * 512 * 128];     // QK f32, shared by BOTH phases
__device__ __half g_scores_h[64 * 512 * 128];   // softmaxed probs (p1, then p2)
__device__ __half g_x_h[64 * 512 * 640];        // attention out half
__device__ __half g_i_h[64 * 512 * 640];        // half(i_batch)
__device__ __half g_q_h[64 * 128 * 640];        // half(q_batch)
__device__ __half g_vT1[64 * 640 * 128];        // q_batch^T half
__device__ __half g_iT[64 * 640 * 512];         // i_batch^T half
__device__ __half g_w1t[1280 * 640];            // lW1^T half
__device__ __half g_iw1t[1280 * 640];           // iW1^T half
__device__ float  g_att[64 * 512];
__device__ float  g_pooled[64 * 640];
__device__ int    g_mask_mode;                  // 0=int32, 1=uint8, 2=float32

// ---------------- helpers ------------------------------------------------------
__device__ __forceinline__ uint32_t s2u(const void* p) {
    return (uint32_t)__cvta_generic_to_shared(p);
}
__device__ __forceinline__ void cp16(uint32_t s, const void* g) {
    asm volatile("cp.async.cg.shared.global [%0], [%1], 16;" :: "r"(s), "l"(g));
}
__device__ __forceinline__ void cp_commit() { asm volatile("cp.async.commit_group;"); }
template <int N> __device__ __forceinline__ void cp_wait() {
    asm volatile("cp.async.wait_group %0;" :: "n"(N));
}
__device__ __forceinline__ void ldsm_x4(uint32_t& r0, uint32_t& r1, uint32_t& r2,
                                        uint32_t& r3, uint32_t addr) {
    asm volatile("ldmatrix.sync.aligned.m8n8.x4.shared.b16 {%0,%1,%2,%3}, [%4];"
                 : "=r"(r0), "=r"(r1), "=r"(r2), "=r"(r3) : "r"(addr));
}
__device__ __forceinline__ void mma_f16(float* c, const uint32_t* a, const uint32_t* b) {
    asm volatile(
        "mma.sync.aligned.m16n8k16.row.col.f32.f16.f16.f32 "
        "{%0,%1,%2,%3},{%4,%5,%6,%7},{%8,%9},{%0,%1,%2,%3};"
        : "+f"(c[0]), "+f"(c[1]), "+f"(c[2]), "+f"(c[3])
        : "r"(a[0]), "r"(a[1]), "r"(a[2]), "r"(a[3]), "r"(b[0]), "r"(b[1]));
}

// ---------------- mask handling ------------------------------------------------
__device__ __forceinline__ bool mask_at(const void* m, size_t idx, int mode) {
    if (mode == 0) return ((const int*)m)[idx] != 0;
    if (mode == 1) return ((const unsigned char*)m)[idx] != 0;
    return ((const float*)m)[idx] != 0.0f;
}

__global__ void detect_mask_kernel(const unsigned int* __restrict__ m, int n_ints) {
    __shared__ int s_i32bad, s_u8bad, s_f32bad;
    if (threadIdx.x == 0) { s_i32bad = 0; s_u8bad = 0; s_f32bad = 0; }
    __syncthreads();
    int i32bad = 0, u8bad = 0, f32bad = 0;
    for (int i = threadIdx.x; i < n_ints; i += blockDim.x) {
        unsigned int v = m[i];
        if (!(v == 0u || v == 1u)) i32bad = 1;
        if ((v & 0xFEFEFEFEu) != 0u) u8bad = 1;
        if (!(v == 0u || v == 0x3F800000u)) f32bad = 1;
    }
    if (i32bad) atomicOr(&s_i32bad, 1);
    if (u8bad)  atomicOr(&s_u8bad, 1);
    if (f32bad) atomicOr(&s_f32bad, 1);
    __syncthreads();
    if (threadIdx.x == 0) {
        int mode;
        if (!s_i32bad)      mode = 0;
        else if (!s_u8bad)  mode = 1;
        else if (!s_f32bad) mode = 2;
        else                mode = 1;
        g_mask_mode = mode;
    }
}

// ---------------- reductions ---------------------------------------------------
__device__ __forceinline__ float warpReduceMax(float v) {
    #pragma unroll
    for (int o = 16; o > 0; o >>= 1) v = fmaxf(v, __shfl_xor_sync(0xffffffffu, v, o));
    return v;
}
__device__ __forceinline__ float warpReduceSum(float v) {
    #pragma unroll
    for (int o = 16; o > 0; o >>= 1) v += __shfl_xor_sync(0xffffffffu, v, o);
    return v;
}
__device__ __forceinline__ float blockReduceMax(float v) {
    __shared__ float s[32];
    int lane = threadIdx.x & 31, wid = threadIdx.x >> 5;
    v = warpReduceMax(v);
    if (lane == 0) s[wid] = v;
    __syncthreads();
    int nw = (blockDim.x + 31) >> 5;
    v = (threadIdx.x < nw) ? s[threadIdx.x] : -INFINITY;
    if (wid == 0) v = warpReduceMax(v);
    if (threadIdx.x == 0) s[0] = v;
    __syncthreads();
    float r = s[0];
    __syncthreads();
    return r;
}
__device__ __forceinline__ float blockReduceSum(float v) {
    __shared__ float s[32];
    int lane = threadIdx.x & 31, wid = threadIdx.x >> 5;
    v = warpReduceSum(v);
    if (lane == 0) s[wid] = v;
    __syncthreads();
    int nw = (blockDim.x + 31) >> 5;
    v = (threadIdx.x < nw) ? s[threadIdx.x] : 0.0f;
    if (wid == 0) v = warpReduceSum(v);
    if (threadIdx.x == 0) s[0] = v;
    __syncthreads();
    float r = s[0];
    __syncthreads();
    return r;
}

// ---------------- FP16 GEMM: 256 thr, 4x2 warps, 32x64 warp tiles ---------------
// C[M,N] = A[M,K] @ B[N,K]^T, half K-major. CTA 128x128, BK=32, 4-stage cp.async.
// EPI: 0 = f32 C; 1 = half Ch; 2 = fused attflat epilogue into f32 C (att).
constexpr int RSH = 40;                       // row stride in halfs (80B)
constexpr int TILEH = 128 * RSH;
constexpr int STAGEH = 2 * TILEH;
constexpr int H16_STAGES = 4;
constexpr int H16_SMEM = H16_STAGES * STAGEH * 2;   // 81920 bytes

template <int EPI>
__global__ __launch_bounds__(256, 2)
void gemm_h16(const __half* __restrict__ A, const __half* __restrict__ B,
              float* __restrict__ C, __half* __restrict__ Ch,
              int M, int N, int K, long sA, long sB, long sC,
              const float* __restrict__ b1, const float* __restrict__ w2)
{
    extern __shared__ __half sm[];
    const uint32_t smem0 = s2u(sm);

    const int bz = blockIdx.z;
    A += (size_t)bz * sA; B += (size_t)bz * sB;
    if (EPI == 0 || EPI == 2) C += (size_t)bz * sC;
    if (EPI == 1) Ch += (size_t)bz * sC;

    const int tid = threadIdx.x;
    const int lane = tid & 31, wid = tid >> 5;
    const int warp_m = wid & 3, warp_n = wid >> 2;   // 4 x 2 warps
    const int wRow = warp_m * 32, wCol = warp_n * 64;
    const int g = lane >> 2, q = lane & 3;
    const int rowBase = blockIdx.y * 128, colBase = blockIdx.x * 128;

    const uint32_t aLane = (uint32_t)(((wRow + (lane & 15)) * RSH + ((lane >> 4) << 3)) * 2);
    const uint32_t bLane = (uint32_t)(TILEH * 2 +
                           ((wCol + (lane & 15)) * RSH + ((lane >> 4) << 3)) * 2);

    const int nt = K / 32;

    auto issue = [&](int t) {
        __half* st = sm + (t % H16_STAGES) * STAGEH;
        const __half* Ag = A + (size_t)rowBase * K + t * 32;
        const __half* Bg = B + (size_t)colBase * K + t * 32;
        #pragma unroll
        for (int l = 0; l < 2; ++l) {
            int id = tid + l * 256;
            int r = id >> 2, c = (id & 3) << 3;
            cp16(s2u(st + r * RSH + c), Ag + (size_t)r * K + c);
            cp16(s2u(st + TILEH + r * RSH + c), Bg + (size_t)r * K + c);
        }
    };

    float acc[2][8][4];
    #pragma unroll
    for (int i = 0; i < 2; i++)
        #pragma unroll
        for (int j = 0; j < 8; j++)
            #pragma unroll
            for (int r = 0; r < 4; r++) acc[i][j][r] = 0.0f;

    issue(0); cp_commit();
    issue(1); cp_commit();
    issue(2); cp_commit();

    for (int kt = 0; kt < nt; ++kt) {
        cp_wait<2>();
        __syncthreads();
        if (kt + 3 < nt) issue(kt + 3);
        cp_commit();

        const uint32_t st = smem0 + (uint32_t)((kt % H16_STAGES) * STAGEH * 2);

        #pragma unroll
        for (int ks = 0; ks < 2; ++ks) {
            const uint32_t ko = (uint32_t)(ks * 32);
            uint32_t af[2][4];
            #pragma unroll
            for (int mt = 0; mt < 2; mt++)
                ldsm_x4(af[mt][0], af[mt][1], af[mt][2], af[mt][3],
                        st + aLane + (uint32_t)(mt * 16 * RSH * 2) + ko);
            uint32_t bf[8][2];
            #pragma unroll
            for (int np = 0; np < 4; np++) {
                uint32_t r0, r1, r2, r3;
                ldsm_x4(r0, r1, r2, r3,
                        st + bLane + (uint32_t)(np * 16 * RSH * 2) + ko);
                bf[2 * np][0] = r0; bf[2 * np + 1][0] = r1;
                bf[2 * np][1] = r2; bf[2 * np + 1][1] = r3;
            }
            #pragma unroll
            for (int mt = 0; mt < 2; mt++)
                #pragma unroll
                for (int nn = 0; nn < 8; nn++)
                    mma_f16(acc[mt][nn], af[mt], bf[nn]);
        }
    }

    if (EPI == 2) {
        float bb[8][2], ww[8][2];
        #pragma unroll
        for (int nn = 0; nn < 8; nn++) {
            int col = colBase + wCol + nn * 8 + 2 * q;
            bb[nn][0] = b1[col];     bb[nn][1] = b1[col + 1];
            ww[nn][0] = w2[col];     ww[nn][1] = w2[col + 1];
        }
        #pragma unroll
        for (int mt = 0; mt < 2; mt++) {
            float s0 = 0.0f, s1 = 0.0f;
            #pragma unroll
            for (int nn = 0; nn < 8; nn++) {
                float v;
                v = acc[mt][nn][0] + bb[nn][0]; if (v > 0.0f) s0 += v * ww[nn][0];
                v = acc[mt][nn][1] + bb[nn][1]; if (v > 0.0f) s0 += v * ww[nn][1];
                v = acc[mt][nn][2] + bb[nn][0]; if (v > 0.0f) s1 += v * ww[nn][0];
                v = acc[mt][nn][3] + bb[nn][1]; if (v > 0.0f) s1 += v * ww[nn][1];
            }
            s0 += __shfl_xor_sync(0xffffffffu, s0, 1);
            s0 += __shfl_xor_sync(0xffffffffu, s0, 2);
            s1 += __shfl_xor_sync(0xffffffffu, s1, 1);
            s1 += __shfl_xor_sync(0xffffffffu, s1, 2);
            if (q == 0) {
                int row = rowBase + wRow + mt * 16 + g;
                atomicAdd(&C[row], s0);
                atomicAdd(&C[row + 8], s1);
            }
        }
    } else if (EPI == 1) {
        #pragma unroll
        for (int mt = 0; mt < 2; mt++) {
            int row = rowBase + wRow + mt * 16 + g;
            #pragma unroll
            for (int nn = 0; nn < 8; nn++) {
                int col = colBase + wCol + nn * 8 + 2 * q;
                *(__half2*)(Ch + (size_t)row * N + col) =
                    __floats2half2_rn(acc[mt][nn][0], acc[mt][nn][1]);
                *(__half2*)(Ch + (size_t)(row + 8) * N + col) =
                    __floats2half2_rn(acc[mt][nn][2], acc[mt][nn][3]);
            }
        }
    } else {
        #pragma unroll
        for (int mt = 0; mt < 2; mt++) {
            int row = rowBase + wRow + mt * 16 + g;
            #pragma unroll
            for (int nn = 0; nn < 8; nn++) {
                int col = colBase + wCol + nn * 8 + 2 * q;
                *(float2*)(C + (size_t)row * N + col) =
                    make_float2(acc[mt][nn][0], acc[mt][nn][1]);
                *(float2*)(C + (size_t)(row + 8) * N + col) =
                    make_float2(acc[mt][nn][2], acc[mt][nn][3]);
            }
        }
    }
}

// ---------------- prep: transpose + (optional) straight half copy --------------
// in f32 [z][R][C] -> outT half [z][C][R]; if outC != nullptr also half [z][R][C].
__global__ void prep_kernel(const float* __restrict__ in, __half* __restrict__ outT,
                            __half* __restrict__ outC, int R, int C)
{
    __shared__ float t[32][33];
    const size_t zo = (size_t)blockIdx.z * R * C;
    const int c0 = blockIdx.x * 32, r0 = blockIdx.y * 32;
    #pragma unroll
    for (int i = threadIdx.y; i < 32; i += 8) {
        float v = in[zo + (size_t)(r0 + i) * C + c0 + threadIdx.x];
        t[i][threadIdx.x] = v;
        if (outC) outC[zo + (size_t)(r0 + i) * C + c0 + threadIdx.x] = __float2half_rn(v);
    }
    __syncthreads();
    #pragma unroll
    for (int i = threadIdx.y; i < 32; i += 8)
        outT[zo + (size_t)(c0 + i) * R + r0 + threadIdx.x] =
            __float2half_rn(t[threadIdx.x][i]);
}

// ---------------- softmaxes -----------------------------------------------------
// direct: row-major scores [.., Nk]; mask over k.
__global__ void attn_softmax_h(const float* __restrict__ scores,
                               __half* __restrict__ outh,
                               const void* __restrict__ mask,
                               int rowsPerBatch, int Nk, float scale)
{
    const int row = blockIdx.x;
    const int b = row / rowsPerBatch;
    const int mode = g_mask_mode;
    const float* s = scores + (size_t)row * Nk;
    __half* o = outh + (size_t)row * Nk;
    const int vpt = Nk >> 7;

    float v[4];
    float lmax = -INFINITY;
    for (int j = 0; j < vpt; ++j) {
        int k = threadIdx.x + (j << 7);
        float x = mask_at(mask, (size_t)b * Nk + k, mode) ? NEGV : s[k] * scale;
        v[j] = x;
        lmax = fmaxf(lmax, x);
    }
    float rmax = blockReduceMax(lmax);
    float lsum = 0.0f;
    for (int j = 0; j < vpt; ++j) {
        v[j] = __expf(v[j] - rmax);
        lsum += v[j];
    }
    float inv = 1.0f / blockReduceSum(lsum);
    for (int j = 0; j < vpt; ++j)
        o[threadIdx.x + (j << 7)] = __float2half_rn(v[j] * inv);
}

// transposed: scores laid out [b][k][q] (Nk x Q); row handles (b,q); reads column q.
__global__ void attn_softmax_hT(const float* __restrict__ scores,
                                __half* __restrict__ outh,
                                const void* __restrict__ mask,
                                int Q, int Nk, float scale)
{
    const int row = blockIdx.x;        // b*Q + q
    const int b = row / Q;
    const int qq = row - b * Q;
    const int mode = g_mask_mode;
    const float* s = scores + (size_t)b * Nk * Q + qq;
    __half* o = outh + (size_t)row * Nk;
    const int vpt = Nk >> 7;           // 4 for Nk=512

    float v[4];
    float lmax = -INFINITY;
    for (int j = 0; j < vpt; ++j) {
        int k = threadIdx.x + (j << 7);
        float x = mask_at(mask, (size_t)b * Nk + k, mode) ? NEGV : s[(size_t)k * Q] * scale;
        v[j] = x;
        lmax = fmaxf(lmax, x);
    }
    float rmax = blockReduceMax(lmax);
    float lsum = 0.0f;
    for (int j = 0; j < vpt; ++j) {
        v[j] = __expf(v[j] - rmax);
        lsum += v[j];
    }
    float inv = 1.0f / blockReduceSum(lsum);
    for (int j = 0; j < vpt; ++j)
        o[threadIdx.x + (j << 7)] = __float2half_rn(v[j] * inv);
}

// ---------------- fused attflat softmax + pool ------------------------------------
// p = softmax(att with mask) over Nt; pooled[b,:] = sum_t p[t]*x[b,t,:];
// optionally write p to weightOut.
__global__ void flat_softmax_pool(const float* __restrict__ att,
                                  const void* __restrict__ mask,
                                  const __half* __restrict__ x,
                                  float* __restrict__ pooled,
                                  float* __restrict__ weightOut, int Nt)
{
    __shared__ float p[512];
    const int b = blockIdx.x;
    const int mode = g_mask_mode;
    const float* a = att + (size_t)b * Nt;

    float lmax = -INFINITY;
    for (int t = threadIdx.x; t < Nt; t += blockDim.x) {
        float v = mask_at(mask, (size_t)b * Nt + t, mode) ? NEGV : a[t];
        p[t] = v;
        lmax = fmaxf(lmax, v);
    }
    float rmax = blockReduceMax(lmax);
    float lsum = 0.0f;
    for (int t = threadIdx.x; t < Nt; t += blockDim.x) {
        float e = __expf(p[t] - rmax);
        p[t] = e;
        lsum += e;
    }
    float inv = 1.0f / blockReduceSum(lsum);
    for (int t = threadIdx.x; t < Nt; t += blockDim.x) {
        p[t] *= inv;
        if (weightOut) weightOut[(size_t)b * Nt + t] = p[t];
    }
    __syncthreads();

    const __half* xb = x + (size_t)b * Nt * 640;
    for (int d = threadIdx.x; d < 640; d += blockDim.x) {
        float s = 0.0f;
        for (int t = 0; t < Nt; t++) s += p[t] * __half2float(xb[(size_t)t * 640 + d]);
        pooled[(size_t)b * 640 + d] = s;
    }
}

// ---------------- out = pooled @ Wm + bm  (64x640x640) ----------------------------
__global__ void final_linear_kernel(const float* __restrict__ pooled,
                                    const float* __restrict__ Wm,
                                    const float* __restrict__ bm,
                                    float* __restrict__ out)
{
    const int b = blockIdx.x;
    const int n = blockIdx.y * 128 + threadIdx.x;
    __shared__ float p[640];
    for (int i = threadIdx.x; i < 640; i += blockDim.x) p[i] = pooled[(size_t)b * 640 + i];
    __syncthreads();
    float s = bm[n];
    for (int k = 0; k < 640; k++) s += p[k] * Wm[(size_t)k * 640 + n];
    out[(size_t)b * 640 + n] = s;
}

__global__ void zero_kernel(float* __restrict__ p, int n) {
    int i = blockIdx.x * blockDim.x + threadIdx.x;
    if (i < n) p[i] = 0.0f;
}

// ---------------- launch ------------------------------------------------------------
extern "C" void kernel_launch(void* const* d_in, const int* in_sizes, int n_in,
                              void* d_out, int out_size)
{
    const float* i_batch = (const float*)d_in[0];   // [64,512,640]
    const float* q_batch = (const float*)d_in[1];   // [64,128,640]
    const void*  i_mask  = d_in[2];                 // [64,512]
    const void*  q_mask  = d_in[3];                 // [64,128]
    const float* lW1 = (const float*)d_in[4];
    const float* lb1 = (const float*)d_in[5];
    const float* lW2 = (const float*)d_in[6];
    const float* lWm = (const float*)d_in[8];
    const float* lbm = (const float*)d_in[9];
    const float* iW1 = (const float*)d_in[10];
    const float* ib1 = (const float*)d_in[11];
    const float* iW2 = (const float*)d_in[12];
    const float* iWm = (const float*)d_in[14];
    const float* ibm = (const float*)d_in[15];
    float* out = (float*)d_out;                     // i_feat | l_feat | i_weight

    float *scores, *att, *pooled;
    __half *scores_h, *x_h, *i_h, *q_h, *vT1, *iT, *w1t, *iw1t;
    cudaGetSymbolAddress((void**)&scores, g_scores);
    cudaGetSymbolAddress((void**)&scores_h, g_scores_h);
    cudaGetSymbolAddress((void**)&x_h, g_x_h);
    cudaGetSymbolAddress((void**)&i_h, g_i_h);
    cudaGetSymbolAddress((void**)&q_h, g_q_h);
    cudaGetSymbolAddress((void**)&vT1, g_vT1);
    cudaGetSymbolAddress((void**)&iT, g_iT);
    cudaGetSymbolAddress((void**)&w1t, g_w1t);
    cudaGetSymbolAddress((void**)&iw1t, g_iw1t);
    cudaGetSymbolAddress((void**)&att, g_att);
    cudaGetSymbolAddress((void**)&pooled, g_pooled);

    const float scale = 1.0f / sqrtf(640.0f);
    const int B = 64, Ni = 512, Nq = 128, D = 640, H = 1280;

    cudaFuncSetAttribute(gemm_h16<0>, cudaFuncAttributeMaxDynamicSharedMemorySize, H16_SMEM);
    cudaFuncSetAttribute(gemm_h16<1>, cudaFuncAttributeMaxDynamicSharedMemorySize, H16_SMEM);
    cudaFuncSetAttribute(gemm_h16<2>, cudaFuncAttributeMaxDynamicSharedMemorySize, H16_SMEM);

    detect_mask_kernel<<<1, 256>>>((const unsigned int*)i_mask, 8192);

    // ---- prep: transposes + half copies (batches read once) ----
    prep_kernel<<<dim3(D / 32, Ni / 32, B), dim3(32, 8)>>>(i_batch, iT, i_h, Ni, D);
    prep_kernel<<<dim3(D / 32, Nq / 32, B), dim3(32, 8)>>>(q_batch, vT1, q_h, Nq, D);
    prep_kernel<<<dim3(H / 32, D / 32, 1), dim3(32, 8)>>>(lW1, w1t, nullptr, D, H);
    prep_kernel<<<dim3(H / 32, D / 32, 1), dim3(32, 8)>>>(iW1, iw1t, nullptr, D, H);

    // ===== shared QK: scores[b,i,q] = i_batch . q_batch  (used by BOTH phases) =====
    gemm_h16<0><<<dim3(1, 4, B), 256, H16_SMEM>>>(
        i_h, q_h, scores, nullptr, Ni, Nq, D,
        (long)Ni * D, (long)Nq * D, (long)Ni * Nq, nullptr, nullptr);

    // ===== Phase 1: softmax over q (mask=q_mask), PV1, attflat(lW*) =====
    attn_softmax_h<<<B * Ni, 128>>>(scores, scores_h, q_mask, Ni, Nq, scale);
    gemm_h16<1><<<dim3(5, 4, B), 256, H16_SMEM>>>(
        scores_h, vT1, nullptr, x_h, Ni, D, Nq,
        (long)Ni * Nq, (long)D * Nq, (long)Ni * D, nullptr, nullptr);

    zero_kernel<<<(B * Ni + 255) / 256, 256>>>(att, B * Ni);
    gemm_h16<2><<<dim3(H / 128, (B * Ni) / 128, 1), 256, H16_SMEM>>>(
        x_h, w1t, att, nullptr, B * Ni, H, D, 0, 0, 0, lb1, lW2);
    flat_softmax_pool<<<B, 256>>>(att, i_mask, x_h, pooled, out + 2 * B * D, Ni);
    final_linear_kernel<<<dim3(B, 5), 128>>>(pooled, lWm, lbm, out);     // i_feat

    // ===== Phase 3: softmax over i on scores^T (mask=i_mask), PV2, attflat(iW*) ====
    attn_softmax_hT<<<B * Nq, 128>>>(scores, scores_h, i_mask, Nq, Ni, scale);
    gemm_h16<1><<<dim3(5, 1, B), 256, H16_SMEM>>>(
        scores_h, iT, nullptr, x_h, Nq, D, Ni,
        (long)Nq * Ni, (long)D * Ni, (long)Nq * D, nullptr, nullptr);

    zero_kernel<<<(B * Nq + 255) / 256, 256>>>(att, B * Nq);
    gemm_h16<2><<<dim3(H / 128, (B * Nq) / 128, 1), 256, H16_SMEM>>>(
        x_h, iw1t, att, nullptr, B * Nq, H, D, 0, 0, 0, ib1, iW2);
    flat_softmax_pool<<<B, 256>>>(att, q_mask, x_h, pooled, nullptr, Nq);
    final_linear_kernel<<<dim3(B, 5), 128>>>(pooled, iWm, ibm, out + B * D);  // l_feat
}